// round 17
// baseline (speedup 1.0000x reference)
#include <cuda_runtime.h>
#include <cuda_fp16.h>
#include <cstdint>

#define Bb   4
#define Nn   2048
#define DM   512
#define Hh   8
#define DH   64
#define SCALE_F 0.125f
#define LOG2E 1.4426950408889634f

#define GEMMH_SMEM 73728   // 3 stages x (A 16KB + B 8KB)
#define FLASH_SMEM 49152   // 2 stages x (K 8KB + V 8KB) + Q 16KB

// ---- scratch (static __device__, allocation-free) ----
__device__ __half g_G [(size_t)Bb * Nn * Nn];          // log2-gate, fp16
__device__ __half g_Qh[(size_t)Bb * Hh * Nn * DH];
__device__ __half g_K [(size_t)Bb * Hh * Nn * DH];
__device__ __half g_V [(size_t)Bb * Hh * Nn * DH];
__device__ __half g_AO[(size_t)Bb * Nn * DM];
__device__ __half g_Wh[(size_t)4 * DM * DM];
__device__ __half g_A0[(size_t)Bb * Nn * DM];
__device__ __half g_A1[(size_t)Bb * Nn * DM];

// ---- helpers ----
__device__ __forceinline__ unsigned u(float x) { return __float_as_uint(x); }
__device__ __forceinline__ unsigned pack2(float lo, float hi) {
    __half2 h = __floats2half2_rn(lo, hi);
    return *reinterpret_cast<unsigned*>(&h);
}
__device__ __forceinline__ unsigned ex2h2(unsigned x) {
    unsigned r;
    asm("ex2.approx.f16x2 %0, %1;" : "=r"(r) : "r"(x));
    return r;
}

#define CP16(dst, src) \
    asm volatile("cp.async.cg.shared.global [%0], [%1], 16;" :: "r"(dst), "l"(src))

__device__ __forceinline__ void mma_f16(float& d0, float& d1, float& d2, float& d3,
                                        unsigned a0, unsigned a1, unsigned a2, unsigned a3,
                                        unsigned b0, unsigned b1) {
    asm volatile(
        "mma.sync.aligned.m16n8k16.row.col.f32.f16.f16.f32 "
        "{%0,%1,%2,%3}, {%4,%5,%6,%7}, {%8,%9}, {%0,%1,%2,%3};"
        : "+f"(d0), "+f"(d1), "+f"(d2), "+f"(d3)
        : "r"(a0), "r"(a1), "r"(a2), "r"(a3), "r"(b0), "r"(b1));
}

__device__ __forceinline__ void ldsm4(unsigned& r0, unsigned& r1, unsigned& r2, unsigned& r3,
                                      unsigned addr) {
    asm volatile("ldmatrix.sync.aligned.m8n8.x4.shared.b16 {%0,%1,%2,%3}, [%4];"
                 : "=r"(r0), "=r"(r1), "=r"(r2), "=r"(r3) : "r"(addr));
}
__device__ __forceinline__ void ldsm4t(unsigned& r0, unsigned& r1, unsigned& r2, unsigned& r3,
                                       unsigned addr) {
    asm volatile("ldmatrix.sync.aligned.m8n8.x4.trans.shared.b16 {%0,%1,%2,%3}, [%4];"
                 : "=r"(r0), "=r"(r1), "=r"(r2), "=r"(r3) : "r"(addr));
}

// ============================================================
// Kernel A: fused f32->fp16 converts AND gate precompute (R16)
// ============================================================
__global__ void prep_all(const float4* __restrict__ Wq, const float4* __restrict__ Wk,
                         const float4* __restrict__ Wv, const float4* __restrict__ Wo,
                         const float4* __restrict__ Qin, const float4* __restrict__ KVin,
                         const float4* __restrict__ SC,
                         const float* __restrict__ gw, const float* __restrict__ gb) {
    int b = blockIdx.x;
    if (b >= 9216) {
        int i = (b - 9216) * 256 + threadIdx.x;
        float w = __ldg(gw), bia = __ldg(gb);
        float4 s = SC[i];
        float rx = __log2f(__fdividef(1.f, 1.f + __expf(-(s.x * w + bia))) + 1e-8f);
        float ry = __log2f(__fdividef(1.f, 1.f + __expf(-(s.y * w + bia))) + 1e-8f);
        float rz = __log2f(__fdividef(1.f, 1.f + __expf(-(s.z * w + bia))) + 1e-8f);
        float rw = __log2f(__fdividef(1.f, 1.f + __expf(-(s.w * w + bia))) + 1e-8f);
        uint2 o;
        o.x = pack2(rx, ry);
        o.y = pack2(rz, rw);
        reinterpret_cast<uint2*>(g_G)[i] = o;
        return;
    }
    const float4* src;
    uint2* dst;
    int i;
    if (b < 1024) {
        int seg = b >> 8;
        i = (b & 255) * 256 + threadIdx.x;
        src = (seg == 0) ? Wq : (seg == 1) ? Wk : (seg == 2) ? Wv : Wo;
        dst = reinterpret_cast<uint2*>(g_Wh) + seg * 65536;
    } else if (b < 5120) {
        i = (b - 1024) * 256 + threadIdx.x;
        src = Qin;  dst = reinterpret_cast<uint2*>(g_A0);
    } else {
        i = (b - 5120) * 256 + threadIdx.x;
        src = KVin; dst = reinterpret_cast<uint2*>(g_A1);
    }
    float4 v = src[i];
    uint2 o;
    o.x = pack2(v.x, v.y);
    o.y = pack2(v.z, v.w);
    dst[i] = o;
}

// ============================================================
// Kernel 1: fp16 GEMM, 3-stage cp.async pipeline (R16, unchanged)
// ============================================================
__global__ __launch_bounds__(256, 2) void gemm_h(const float* __restrict__ biasa,
                                                 const float* __restrict__ biasb,
                                                 float* __restrict__ Cext,
                                                 int amode, int cmode) {
    extern __shared__ char smc[];
    unsigned smb;
    asm("{ .reg .u64 t; cvta.to.shared.u64 t, %1; cvt.u32.u64 %0, t; }"
        : "=r"(smb) : "l"(smc));

    const __half* A = (amode == 0) ? g_A0 : (amode == 1 ? g_A1 : g_AO);
    const __half* W;
    const float* bias;
    if (cmode == 0)      { W = g_Wh;                bias = biasa; }
    else if (cmode == 3) { W = g_Wh + 3 * DM * DM;  bias = biasa; }
    else {
        if (blockIdx.x >= 8) { W = g_Wh + 2 * DM * DM; bias = biasb; }
        else                 { W = g_Wh + 1 * DM * DM; bias = biasa; }
    }

    int tid  = threadIdx.x;
    int warp = tid >> 5, lane = tid & 31;
    int g = lane >> 2, tg = lane & 3;
    int wm = warp >> 1, wn = warp & 1;
    int mbase = blockIdx.y * 128, nbase = (blockIdx.x & 7) * 64;

    int srow = tid >> 3, sch = tid & 7;
    int sdoff = ((sch ^ (srow & 7)) << 4);

    int i8 = lane & 7;
    int la = lane & 15, ca = lane >> 4;
    int rowoffB = ((lane >> 4) << 3) + i8;
    int choffB  = (lane >> 3) & 1;

    float acc[2][4][4];
#pragma unroll
    for (int mt = 0; mt < 2; ++mt)
#pragma unroll
        for (int nt = 0; nt < 4; ++nt)
#pragma unroll
            for (int i = 0; i < 4; ++i) acc[mt][nt][i] = 0.f;

#pragma unroll
    for (int p = 0; p < 2; ++p) {
        unsigned Sb = smb + p * 24576;
        int kh = p * 64;
#pragma unroll
        for (int i = 0; i < 4; ++i) {
            int r = srow + 32 * i;
            CP16(Sb + r * 128 + sdoff,
                 (const char*)(A + (size_t)(mbase + r) * 512 + kh) + sch * 16);
        }
#pragma unroll
        for (int i = 0; i < 2; ++i) {
            int r = srow + 32 * i;
            CP16(Sb + 16384 + r * 128 + sdoff,
                 (const char*)(W + (size_t)(nbase + r) * 512 + kh) + sch * 16);
        }
        asm volatile("cp.async.commit_group;");
    }
    asm volatile("cp.async.wait_group 1;" ::: "memory");
    __syncthreads();

#pragma unroll
    for (int kt = 0; kt < 8; ++kt) {
        unsigned Ab = smb + (kt % 3) * 24576;
        unsigned Bsm = Ab + 16384;

        if (kt < 6) {
            unsigned Sn = smb + ((kt + 2) % 3) * 24576;
            int kh = (kt + 2) * 64;
#pragma unroll
            for (int i = 0; i < 4; ++i) {
                int r = srow + 32 * i;
                CP16(Sn + r * 128 + sdoff,
                     (const char*)(A + (size_t)(mbase + r) * 512 + kh) + sch * 16);
            }
#pragma unroll
            for (int i = 0; i < 2; ++i) {
                int r = srow + 32 * i;
                CP16(Sn + 16384 + r * 128 + sdoff,
                     (const char*)(W + (size_t)(nbase + r) * 512 + kh) + sch * 16);
            }
            asm volatile("cp.async.commit_group;");
        }

        unsigned af[2][4][4];
#pragma unroll
        for (int mt = 0; mt < 2; ++mt) {
            int row = wm * 32 + mt * 16 + la;
#pragma unroll
            for (int s = 0; s < 4; ++s)
                ldsm4(af[mt][s][0], af[mt][s][1], af[mt][s][2], af[mt][s][3],
                      Ab + row * 128 + ((((2 * s + ca)) ^ (row & 7)) << 4));
        }

#pragma unroll
        for (int s = 0; s < 4; ++s) {
            unsigned bf[2][4];
#pragma unroll
            for (int ntp = 0; ntp < 2; ++ntp) {
                int rowb = wn * 32 + ntp * 16 + rowoffB;
                ldsm4(bf[ntp][0], bf[ntp][1], bf[ntp][2], bf[ntp][3],
                      Bsm + rowb * 128 + ((((2 * s + choffB)) ^ (rowb & 7)) << 4));
            }
#pragma unroll
            for (int ntp = 0; ntp < 2; ++ntp) {
#pragma unroll
                for (int mt = 0; mt < 2; ++mt) {
                    mma_f16(acc[mt][2 * ntp][0], acc[mt][2 * ntp][1],
                            acc[mt][2 * ntp][2], acc[mt][2 * ntp][3],
                            af[mt][s][0], af[mt][s][1], af[mt][s][2], af[mt][s][3],
                            bf[ntp][0], bf[ntp][1]);
                    mma_f16(acc[mt][2 * ntp + 1][0], acc[mt][2 * ntp + 1][1],
                            acc[mt][2 * ntp + 1][2], acc[mt][2 * ntp + 1][3],
                            af[mt][s][0], af[mt][s][1], af[mt][s][2], af[mt][s][3],
                            bf[ntp][2], bf[ntp][3]);
                }
            }
        }

        if (kt < 6)
            asm volatile("cp.async.wait_group 1;" ::: "memory");
        else if (kt == 6)
            asm volatile("cp.async.wait_group 0;" ::: "memory");
        __syncthreads();
    }

#pragma unroll
    for (int mt = 0; mt < 2; ++mt)
#pragma unroll
        for (int nt = 0; nt < 4; ++nt) {
            int col = nbase + wn * 32 + nt * 8 + 2 * tg;
            float b0 = bias[col], b1 = bias[col + 1];
            int r0 = mbase + wm * 32 + mt * 16 + g;
            int r1 = r0 + 8;
            float v00 = acc[mt][nt][0] + b0, v01 = acc[mt][nt][1] + b1;
            float v10 = acc[mt][nt][2] + b0, v11 = acc[mt][nt][3] + b1;
            if (cmode == 3) {
                *reinterpret_cast<float2*>(Cext + (size_t)r0 * 512 + col) = make_float2(v00, v01);
                *reinterpret_cast<float2*>(Cext + (size_t)r1 * 512 + col) = make_float2(v10, v11);
            } else {
                __half* Ch = (cmode == 0) ? g_Qh : ((blockIdx.x >= 8) ? g_V : g_K);
                int h = col >> 6, d = col & 63;
                {
                    int b = r0 >> 11, n = r0 & 2047;
                    __half* p = Ch + (size_t)(((b << 3) + h) * 2048 + n) * 64 + d;
                    *reinterpret_cast<__half2*>(p) = __floats2half2_rn(v00, v01);
                }
                {
                    int b = r1 >> 11, n = r1 & 2047;
                    __half* p = Ch + (size_t)(((b << 3) + h) * 2048 + n) * 64 + d;
                    *reinterpret_cast<__half2*>(p) = __floats2half2_rn(v10, v11);
                }
            }
        }
}

// ============================================================
// Kernel 2: fp16 flash attention, BM=128 / 128 threads.
//  Each warp owns 32 q-rows (2 m16 tiles) -> K/V fragments loaded
//  ONCE per warp feed 2x the MMAs (smem crossbar was the ceiling).
//  Per-row math order identical to R16 -> bitwise-same result.
// ============================================================
__global__ __launch_bounds__(128, 2) void flash_kernel() {
    extern __shared__ char smc[];
    unsigned smb;
    asm("{ .reg .u64 t; cvta.to.shared.u64 t, %1; cvt.u32.u64 %0, t; }"
        : "=r"(smb) : "l"(smc));

    int tid = threadIdx.x, w = tid >> 5, lane = tid & 31;
    int g = lane >> 2, tg = lane & 3;
    int h = blockIdx.x, qt = blockIdx.y, bz = blockIdx.z;
    int bh = bz * 8 + h;
    const __half* Qb = g_Qh + (size_t)bh * Nn * DH;
    const __half* Kb = g_K  + (size_t)bh * Nn * DH;
    const __half* Vb = g_V  + (size_t)bh * Nn * DH;
    int q0 = qt * 128;

    int srow = tid >> 3, sch = tid & 7;
    int sgoff = srow * 128 + sch * 16;
    int sdoff = srow * 128 + ((sch ^ (srow & 7)) << 4);

    int i8 = lane & 7;
    int la = lane & 15, ca = lane >> 4;
    int rowoff = ((lane >> 4) << 3) + i8;
    int choff = (lane >> 3) & 1;
    int matq = lane >> 3;
    int vrowb = (((matq & 1) << 3) + i8) * 128;
    int chh = matq >> 1;

    // ---- prologue: Q (16KB) + K/V stage0 via cp.async ----
    {
        const char* Qsrc = (const char*)(Qb + (size_t)q0 * 64);
        const char* Ksrc = (const char*)Kb;
        const char* Vsrc = (const char*)Vb;
#pragma unroll
        for (int i = 0; i < 8; ++i)
            CP16(smb + 32768 + sdoff + i * 2048, Qsrc + sgoff + i * 2048);
#pragma unroll
        for (int i = 0; i < 4; ++i) {
            CP16(smb + sdoff + i * 2048,        Ksrc + sgoff + i * 2048);
            CP16(smb + 8192 + sdoff + i * 2048, Vsrc + sgoff + i * 2048);
        }
        asm volatile("cp.async.commit_group;");
        asm volatile("cp.async.wait_group 0;" ::: "memory");
    }
    __syncthreads();

    // Q fragments: 2 m-tiles (rows w*32 .. w*32+31)
    unsigned qa[2][4][4];
#pragma unroll
    for (int mt = 0; mt < 2; ++mt) {
        int qrow = w * 32 + mt * 16 + la;
#pragma unroll
        for (int s = 0; s < 4; ++s)
            ldsm4(qa[mt][s][0], qa[mt][s][1], qa[mt][s][2], qa[mt][s][3],
                  smb + 32768 + qrow * 128 + ((((2 * s + ca)) ^ (qrow & 7)) << 4));
    }

    float accO[2][8][4];
#pragma unroll
    for (int mt = 0; mt < 2; ++mt)
#pragma unroll
        for (int ot = 0; ot < 8; ++ot)
#pragma unroll
            for (int i = 0; i < 4; ++i) accO[mt][ot][i] = 0.f;
    float lacc[2][4] = {{0.f, 0.f, 0.f, 0.f}, {0.f, 0.f, 0.f, 0.f}};
    float mrow[4] = {-1e30f, -1e30f, -1e30f, -1e30f};   // [mt*2 + half]

    const __half* Gm[2][2];
    Gm[0][0] = g_G + ((size_t)bz * Nn + (q0 + w * 32 + g)) * Nn;
    Gm[0][1] = Gm[0][0] + (size_t)8 * Nn;
    Gm[1][0] = Gm[0][0] + (size_t)16 * Nn;
    Gm[1][1] = Gm[0][0] + (size_t)24 * Nn;
    const float SL2 = SCALE_F * LOG2E;
    const unsigned ONES = 0x3C003C00u;

    for (int kt = 0; kt < 32; ++kt) {
        unsigned kb = smb + (kt & 1) * 16384;
        unsigned vb = kb + 8192;

        if (kt < 31) {
            unsigned kbN = smb + ((kt + 1) & 1) * 16384;
            const char* Kn = (const char*)(Kb + (size_t)(kt + 1) * 4096);
            const char* Vn = (const char*)(Vb + (size_t)(kt + 1) * 4096);
#pragma unroll
            for (int i = 0; i < 4; ++i) {
                CP16(kbN + sdoff + i * 2048,        Kn + sgoff + i * 2048);
                CP16(kbN + 8192 + sdoff + i * 2048, Vn + sgoff + i * 2048);
            }
            asm volatile("cp.async.commit_group;");
        }

        // ---- S = Q K^T for both m-tiles (K frags loaded once) ----
        float sacc[2][8][4];
#pragma unroll
        for (int mt = 0; mt < 2; ++mt)
#pragma unroll
            for (int nt = 0; nt < 8; ++nt)
#pragma unroll
                for (int i = 0; i < 4; ++i) sacc[mt][nt][i] = 0.f;
#pragma unroll
        for (int s = 0; s < 4; ++s) {
#pragma unroll
            for (int ntp = 0; ntp < 4; ++ntp) {
                unsigned b0, b1, b2, b3;
                unsigned addr = kb + (unsigned)((16 * ntp + rowoff) * 128
                                + (((2 * s + choff) ^ i8) << 4));
                ldsm4(b0, b1, b2, b3, addr);
#pragma unroll
                for (int mt = 0; mt < 2; ++mt) {
                    mma_f16(sacc[mt][2 * ntp][0], sacc[mt][2 * ntp][1],
                            sacc[mt][2 * ntp][2], sacc[mt][2 * ntp][3],
                            qa[mt][s][0], qa[mt][s][1], qa[mt][s][2], qa[mt][s][3], b0, b1);
                    mma_f16(sacc[mt][2 * ntp + 1][0], sacc[mt][2 * ntp + 1][1],
                            sacc[mt][2 * ntp + 1][2], sacc[mt][2 * ntp + 1][3],
                            qa[mt][s][0], qa[mt][s][1], qa[mt][s][2], qa[mt][s][3], b2, b3);
                }
            }
        }

        // ---- softmax per m-tile (sequential: frees sacc[mt] into pe/po[mt]) ----
        unsigned pe[2][8], po[2][8];
#pragma unroll
        for (int mt = 0; mt < 2; ++mt) {
            int cbase = kt * 64 + 2 * tg;
#pragma unroll
            for (int nt = 0; nt < 8; ++nt) {
                float2 ga = __half22float2(*reinterpret_cast<const __half2*>(Gm[mt][0] + cbase + nt * 8));
                float2 gb2 = __half22float2(*reinterpret_cast<const __half2*>(Gm[mt][1] + cbase + nt * 8));
                sacc[mt][nt][0] = sacc[mt][nt][0] * SL2 + ga.x;
                sacc[mt][nt][1] = sacc[mt][nt][1] * SL2 + ga.y;
                sacc[mt][nt][2] = sacc[mt][nt][2] * SL2 + gb2.x;
                sacc[mt][nt][3] = sacc[mt][nt][3] * SL2 + gb2.y;
            }
            float m0 = mrow[2 * mt], m1 = mrow[2 * mt + 1];
            float mn0 = m0, mn1 = m1;
#pragma unroll
            for (int nt = 0; nt < 8; ++nt) {
                mn0 = fmaxf(mn0, fmaxf(sacc[mt][nt][0], sacc[mt][nt][1]));
                mn1 = fmaxf(mn1, fmaxf(sacc[mt][nt][2], sacc[mt][nt][3]));
            }
            mn0 = fmaxf(mn0, __shfl_xor_sync(0xffffffffu, mn0, 1));
            mn0 = fmaxf(mn0, __shfl_xor_sync(0xffffffffu, mn0, 2));
            mn1 = fmaxf(mn1, __shfl_xor_sync(0xffffffffu, mn1, 1));
            mn1 = fmaxf(mn1, __shfl_xor_sync(0xffffffffu, mn1, 2));
            float al0 = exp2f(m0 - mn0), al1 = exp2f(m1 - mn1);
            mrow[2 * mt] = mn0; mrow[2 * mt + 1] = mn1;
#pragma unroll
            for (int ot = 0; ot < 8; ++ot) {
                accO[mt][ot][0] *= al0; accO[mt][ot][1] *= al0;
                accO[mt][ot][2] *= al1; accO[mt][ot][3] *= al1;
            }
            lacc[mt][0] *= al0; lacc[mt][1] *= al0;
            lacc[mt][2] *= al1; lacc[mt][3] *= al1;
#pragma unroll
            for (int nt = 0; nt < 8; ++nt) {
                pe[mt][nt] = ex2h2(pack2(sacc[mt][nt][0] - mn0, sacc[mt][nt][1] - mn0));
                po[mt][nt] = ex2h2(pack2(sacc[mt][nt][2] - mn1, sacc[mt][nt][3] - mn1));
            }
        }

        // ---- O += P@V ; l += P@ones (V frags loaded once, used by both mt) ----
#pragma unroll
        for (int s = 0; s < 4; ++s) {
#pragma unroll
            for (int mt = 0; mt < 2; ++mt)
                mma_f16(lacc[mt][0], lacc[mt][1], lacc[mt][2], lacc[mt][3],
                        pe[mt][2 * s], po[mt][2 * s], pe[mt][2 * s + 1], po[mt][2 * s + 1],
                        ONES, ONES);
            unsigned base_s = vb + s * 2048 + vrowb;
#pragma unroll
            for (int otp = 0; otp < 4; ++otp) {
                unsigned b0, b1, b2, b3;
                ldsm4t(b0, b1, b2, b3, base_s + ((((2 * otp + chh) ^ i8)) << 4));
#pragma unroll
                for (int mt = 0; mt < 2; ++mt) {
                    mma_f16(accO[mt][2 * otp][0], accO[mt][2 * otp][1],
                            accO[mt][2 * otp][2], accO[mt][2 * otp][3],
                            pe[mt][2 * s], po[mt][2 * s], pe[mt][2 * s + 1], po[mt][2 * s + 1],
                            b0, b1);
                    mma_f16(accO[mt][2 * otp + 1][0], accO[mt][2 * otp + 1][1],
                            accO[mt][2 * otp + 1][2], accO[mt][2 * otp + 1][3],
                            pe[mt][2 * s], po[mt][2 * s], pe[mt][2 * s + 1], po[mt][2 * s + 1],
                            b2, b3);
                }
            }
        }

        if (kt < 31)
            asm volatile("cp.async.wait_group 0;" ::: "memory");
        __syncthreads();
    }

    // epilogue: 32 rows per warp
#pragma unroll
    for (int mt = 0; mt < 2; ++mt) {
        float inv0 = 1.0f / lacc[mt][0], inv1 = 1.0f / lacc[mt][2];
        int qr0 = q0 + w * 32 + mt * 16 + g, qr1 = qr0 + 8;
        __half* O0 = g_AO + ((size_t)(bz * Nn + qr0)) * DM + h * 64;
        __half* O1 = g_AO + ((size_t)(bz * Nn + qr1)) * DM + h * 64;
#pragma unroll
        for (int ot = 0; ot < 8; ++ot) {
            int d = ot * 8 + 2 * tg;
            *reinterpret_cast<__half2*>(O0 + d) = __floats2half2_rn(accO[mt][ot][0] * inv0, accO[mt][ot][1] * inv0);
            *reinterpret_cast<__half2*>(O1 + d) = __floats2half2_rn(accO[mt][ot][2] * inv1, accO[mt][ot][3] * inv1);
        }
    }
}

// ============================================================
extern "C" void kernel_launch(void* const* d_in, const int* in_sizes, int n_in,
                              void* d_out, int out_size) {
    const float* Qin  = (const float*)d_in[0];
    const float* KVin = (const float*)d_in[1];
    const float* SC   = (const float*)d_in[2];
    const float* Wq   = (const float*)d_in[3];
    const float* Wqb  = (const float*)d_in[4];
    const float* Wk   = (const float*)d_in[5];
    const float* Wkb  = (const float*)d_in[6];
    const float* Wv   = (const float*)d_in[7];
    const float* Wvb  = (const float*)d_in[8];
    const float* gw   = (const float*)d_in[9];
    const float* gb   = (const float*)d_in[10];
    const float* Wo   = (const float*)d_in[11];
    const float* Wob  = (const float*)d_in[12];
    float* out = (float*)d_out;

    cudaFuncSetAttribute(gemm_h,       cudaFuncAttributeMaxDynamicSharedMemorySize, GEMMH_SMEM);
    cudaFuncSetAttribute(flash_kernel, cudaFuncAttributeMaxDynamicSharedMemorySize, FLASH_SMEM);

    prep_all<<<25600, 256>>>(reinterpret_cast<const float4*>(Wq),
                             reinterpret_cast<const float4*>(Wk),
                             reinterpret_cast<const float4*>(Wv),
                             reinterpret_cast<const float4*>(Wo),
                             reinterpret_cast<const float4*>(Qin),
                             reinterpret_cast<const float4*>(KVin),
                             reinterpret_cast<const float4*>(SC), gw, gb);

    gemm_h<<<dim3(8, 64),  256, GEMMH_SMEM>>>(Wqb, nullptr, nullptr, 0, 0);
    gemm_h<<<dim3(16, 64), 256, GEMMH_SMEM>>>(Wkb, Wvb,     nullptr, 1, 4);

    flash_kernel<<<dim3(8, 16, 4), 128, FLASH_SMEM>>>();

    gemm_h<<<dim3(8, 64),  256, GEMMH_SMEM>>>(Wob, nullptr, out, 2, 3);
}